// round 1
// baseline (speedup 1.0000x reference)
#include <cuda_runtime.h>
#include <math.h>

// Problem shape (fixed by the dataset):
//   x: [16, 2048, 1024] fp32   -> A [M=32768, K=1024]
//   W: [1024, 3072]     fp32   -> [K, N=3072]
//   b: [3072]           fp32
//   out h: [16, 2048, 1024] fp32
#define M_DIM 32768
#define K_DIM 1024
#define N_DIM 3072
#define H_DIM 1024
#define T_DIM 2048
#define B_DIM 16

// Scratch for u = x@W + b (activations pre-applied to f,r thirds).
// 32768 * 3072 floats = 402.7 MB, static device allocation (no cudaMalloc allowed).
__device__ float g_u[(size_t)M_DIM * N_DIM];

// ---------------------------------------------------------------------------
// GEMM: 128x128 block tile, BK=8, 256 threads, 8x8 per-thread microtile.
// Epilogue: +bias, sigmoid on columns [H, 3H).
// ---------------------------------------------------------------------------
__global__ __launch_bounds__(256) void sru_gemm_kernel(
    const float* __restrict__ A,
    const float* __restrict__ W,
    const float* __restrict__ bias)
{
    __shared__ float As[8][132];   // [k][m], padded to 132 (16B-aligned rows, conflict-light)
    __shared__ float Bs[8][128];   // [k][n]

    const int tid = threadIdx.x;
    const int m0 = blockIdx.y * 128;
    const int n0 = blockIdx.x * 128;

    // Global->shared load mapping
    const int a_row = tid >> 1;          // 0..127 (m within tile)
    const int a_q   = (tid & 1) * 4;     // k offset 0 or 4
    const int b_row = tid >> 5;          // 0..7   (k within tile)
    const int b_col = (tid & 31) * 4;    // n within tile

    // Compute mapping: 16x16 thread grid, each 8x8
    const int tx = tid & 15;
    const int ty = tid >> 4;

    const float* Aptr = A + (size_t)(m0 + a_row) * K_DIM + a_q;
    const float* Wptr = W + (size_t)b_row * N_DIM + n0 + b_col;

    float acc[8][8];
#pragma unroll
    for (int i = 0; i < 8; i++)
#pragma unroll
        for (int j = 0; j < 8; j++) acc[i][j] = 0.0f;

    for (int k0 = 0; k0 < K_DIM; k0 += 8) {
        float4 av = *reinterpret_cast<const float4*>(Aptr + k0);
        float4 bv = *reinterpret_cast<const float4*>(Wptr + (size_t)k0 * N_DIM);

        __syncthreads();   // protect previous tile's reads
        As[a_q + 0][a_row] = av.x;
        As[a_q + 1][a_row] = av.y;
        As[a_q + 2][a_row] = av.z;
        As[a_q + 3][a_row] = av.w;
        *reinterpret_cast<float4*>(&Bs[b_row][b_col]) = bv;
        __syncthreads();

#pragma unroll
        for (int k = 0; k < 8; k++) {
            float a_frag[8], b_frag[8];
            *reinterpret_cast<float4*>(&a_frag[0]) = *reinterpret_cast<const float4*>(&As[k][ty * 8]);
            *reinterpret_cast<float4*>(&a_frag[4]) = *reinterpret_cast<const float4*>(&As[k][ty * 8 + 4]);
            *reinterpret_cast<float4*>(&b_frag[0]) = *reinterpret_cast<const float4*>(&Bs[k][tx * 8]);
            *reinterpret_cast<float4*>(&b_frag[4]) = *reinterpret_cast<const float4*>(&Bs[k][tx * 8 + 4]);
#pragma unroll
            for (int i = 0; i < 8; i++)
#pragma unroll
                for (int j = 0; j < 8; j++)
                    acc[i][j] = fmaf(a_frag[i], b_frag[j], acc[i][j]);
        }
    }

    // Epilogue: bias + sigmoid for f/r thirds, vectorized store into g_u
#pragma unroll
    for (int i = 0; i < 8; i++) {
        const int m = m0 + ty * 8 + i;
#pragma unroll
        for (int j4 = 0; j4 < 8; j4 += 4) {
            float4 v;
            float* vp = &v.x;
#pragma unroll
            for (int j = 0; j < 4; j++) {
                const int n = n0 + tx * 8 + j4 + j;
                float val = acc[i][j4 + j] + bias[n];
                if (n >= H_DIM) {
                    val = 1.0f / (1.0f + __expf(-val));   // sigmoid for f and r
                }
                vp[j] = val;
            }
            *reinterpret_cast<float4*>(&g_u[(size_t)m * N_DIM + n0 + tx * 8 + j4]) = v;
        }
    }
}

// ---------------------------------------------------------------------------
// Sequential SRU scan: one thread per (b, h) channel, 16384 threads total.
// c_t = f_t*c_{t-1} + (1-f_t)*x_t ;  h_t = r_t*tanh(c_t) + (1-r_t)*x_t
// f,r already sigmoid'ed by the GEMM epilogue.
// ---------------------------------------------------------------------------
__global__ __launch_bounds__(64) void sru_scan_kernel(float* __restrict__ Hout)
{
    const int idx = blockIdx.x * blockDim.x + threadIdx.x;  // 0..16383
    const int b = idx >> 10;        // / H_DIM
    const int h = idx & (H_DIM - 1);

    const float* up = g_u + (size_t)b * T_DIM * N_DIM + h;
    float* op = Hout + (size_t)b * T_DIM * H_DIM + h;

    float c = 0.0f;
    for (int t = 0; t < T_DIM; t += 4) {
        float xt[4], ft[4], rt[4];
#pragma unroll
        for (int i = 0; i < 4; i++) {
            const float* p = up + (size_t)(t + i) * N_DIM;
            xt[i] = p[0];
            ft[i] = p[H_DIM];
            rt[i] = p[2 * H_DIM];
        }
#pragma unroll
        for (int i = 0; i < 4; i++) {
            // c = f*c + (1-f)*x  (single FFMA in the dependent chain)
            const float g = (1.0f - ft[i]) * xt[i];
            c = fmaf(ft[i], c, g);
            const float hv = fmaf(rt[i], tanhf(c) - xt[i], xt[i]); // r*tanh(c) + (1-r)*x
            op[(size_t)(t + i) * H_DIM] = hv;
        }
    }
}

extern "C" void kernel_launch(void* const* d_in, const int* in_sizes, int n_in,
                              void* d_out, int out_size)
{
    const float* x = (const float*)d_in[0];   // [16,2048,1024]
    const float* W = (const float*)d_in[1];   // [1024,3072]
    const float* b = (const float*)d_in[2];   // [3072]
    float* out = (float*)d_out;               // [16,2048,1024]

    dim3 gemm_grid(N_DIM / 128, M_DIM / 128); // (24, 256)
    sru_gemm_kernel<<<gemm_grid, 256>>>(x, W, b);

    sru_scan_kernel<<<(B_DIM * H_DIM) / 64, 64>>>(out);
}

// round 3
// speedup vs baseline: 2.2009x; 2.2009x over previous
#include <cuda_runtime.h>
#include <cuda_bf16.h>
#include <math.h>
#include <stdint.h>

// Shapes (fixed by dataset)
#define M_DIM 32768
#define K_DIM 1024
#define N_DIM 3072
#define H_DIM 1024
#define T_DIM 2048
#define B_DIM 16

#define KTOT 3072            // K' = 3 * 1024 (hi|lo|hi split)
#define BM 128
#define BN 256
#define BK 64                // bf16 elems per chunk = 128 bytes
#define NCH (KTOT / BK)      // 48
#define NSTG 3
#define A_ST (BM * 128)      // 16384 B per stage
#define B_ST (BN * 128)      // 32768 B per stage
#define STG (A_ST + B_ST)
#define GEMM_SMEM (NSTG * STG)   // 147456 B

// ---------------------------------------------------------------------------
// Static device scratch (cudaMalloc forbidden)
// ---------------------------------------------------------------------------
__device__ float g_u[(size_t)M_DIM * N_DIM];                         // 403 MB
__device__ __nv_bfloat16 g_a2[(size_t)M_DIM * KTOT];                 // 201 MB  [m][k']
__device__ __nv_bfloat16 g_b2t[(size_t)N_DIM * KTOT];                // 19 MB   [n][k']

// ---------------------------------------------------------------------------
// PTX helpers (plain sm_103 features only: cp.async, ldmatrix, mma.sync)
// ---------------------------------------------------------------------------
__device__ __forceinline__ uint32_t smem_u32(const void* p) {
    uint32_t a;
    asm("{ .reg .u64 t; cvta.to.shared.u64 t, %1; cvt.u32.u64 %0, t; }" : "=r"(a) : "l"(p));
    return a;
}
#define CP_ASYNC16(s, g) asm volatile("cp.async.cg.shared.global [%0], [%1], 16;" :: "r"(s), "l"(g) : "memory")
#define CP_COMMIT() asm volatile("cp.async.commit_group;" ::: "memory")
#define CP_WAIT1()  asm volatile("cp.async.wait_group 1;" ::: "memory")

__device__ __forceinline__ void ldsm_x4(uint32_t* r, uint32_t addr) {
    asm volatile("ldmatrix.sync.aligned.m8n8.x4.shared.b16 {%0,%1,%2,%3}, [%4];"
                 : "=r"(r[0]), "=r"(r[1]), "=r"(r[2]), "=r"(r[3]) : "r"(addr));
}
__device__ __forceinline__ void mma_bf16(float* d, const uint32_t* a, uint32_t b0, uint32_t b1) {
    asm volatile("mma.sync.aligned.m16n8k16.row.col.f32.bf16.bf16.f32 "
                 "{%0,%1,%2,%3},{%4,%5,%6,%7},{%8,%9},{%0,%1,%2,%3};"
                 : "+f"(d[0]), "+f"(d[1]), "+f"(d[2]), "+f"(d[3])
                 : "r"(a[0]), "r"(a[1]), "r"(a[2]), "r"(a[3]), "r"(b0), "r"(b1));
}
#define SWZ128(off) ((off) ^ (((off) >> 3) & 0x70))

// ---------------------------------------------------------------------------
// Conversions: hi/lo bf16 split, K' = [hi | lo | hi] for A, [hi | hi | lo] for W^T
// ---------------------------------------------------------------------------
__global__ __launch_bounds__(256) void convert_x_kernel(const float* __restrict__ x) {
    size_t i = ((size_t)blockIdx.x * 256 + threadIdx.x) * 4;
    size_t m = i >> 10;
    int k = (int)(i & 1023);
    float4 v = *reinterpret_cast<const float4*>(x + i);
    const float* vp = &v.x;
    unsigned short hi[4], lo[4];
#pragma unroll
    for (int j = 0; j < 4; j++) {
        __nv_bfloat16 h = __float2bfloat16(vp[j]);
        __nv_bfloat16 l = __float2bfloat16(vp[j] - __bfloat162float(h));
        hi[j] = __bfloat16_as_ushort(h);
        lo[j] = __bfloat16_as_ushort(l);
    }
    uint2 hv = make_uint2((uint32_t)hi[0] | ((uint32_t)hi[1] << 16),
                          (uint32_t)hi[2] | ((uint32_t)hi[3] << 16));
    uint2 lv = make_uint2((uint32_t)lo[0] | ((uint32_t)lo[1] << 16),
                          (uint32_t)lo[2] | ((uint32_t)lo[3] << 16));
    __nv_bfloat16* base = g_a2 + m * KTOT;
    *reinterpret_cast<uint2*>(base + k) = hv;              // hi
    *reinterpret_cast<uint2*>(base + 1024 + k) = lv;       // lo
    *reinterpret_cast<uint2*>(base + 2048 + k) = hv;       // hi (dup)
}

__global__ __launch_bounds__(1024) void convert_w_kernel(const float* __restrict__ W) {
    __shared__ float s[32][33];
    int tx = threadIdx.x, ty = threadIdx.y;
    int n0 = blockIdx.x * 32, k0 = blockIdx.y * 32;
    s[ty][tx] = W[(size_t)(k0 + ty) * N_DIM + n0 + tx];
    __syncthreads();
    float v = s[tx][ty];                 // W[k0+tx][n0+ty]
    __nv_bfloat16 h = __float2bfloat16(v);
    __nv_bfloat16 l = __float2bfloat16(v - __bfloat162float(h));
    __nv_bfloat16* base = g_b2t + (size_t)(n0 + ty) * KTOT;
    base[k0 + tx] = h;                   // hi
    base[1024 + k0 + tx] = h;            // hi (dup)
    base[2048 + k0 + tx] = l;            // lo
}

// ---------------------------------------------------------------------------
// mma.sync bf16 GEMM: CTA 128x256, warp 64x64, BK=64, 3-stage cp.async
// Epilogue: +bias, sigmoid on n >= 1024; writes fp32 u.
// ---------------------------------------------------------------------------
__global__ __launch_bounds__(256, 1) void sru_gemm_mma_kernel(const float* __restrict__ bias) {
    extern __shared__ __align__(1024) char dsmem[];
    const uint32_t smem_base = smem_u32(dsmem);

    const int tid = threadIdx.x;
    const int lane = tid & 31;
    const int wid = tid >> 5;
    const int wm = wid & 1;          // 2 warps along M
    const int wn = wid >> 1;         // 4 warps along N
    const int m0 = blockIdx.y * BM;
    const int n0 = blockIdx.x * BN;

    const char* gA = reinterpret_cast<const char*>(g_a2) + (size_t)m0 * (KTOT * 2);
    const char* gB = reinterpret_cast<const char*>(g_b2t) + (size_t)n0 * (KTOT * 2);

    // Per-thread cp.async offsets (row pitch 128 B in smem, KTOT*2 B in gmem)
    uint32_t sAo[4]; size_t gAo[4];
#pragma unroll
    for (int i = 0; i < 4; i++) {
        int u = i * 256 + tid, row = u >> 3, un = u & 7;
        sAo[i] = SWZ128((uint32_t)(row * 128 + un * 16));
        gAo[i] = (size_t)row * (KTOT * 2) + un * 16;
    }
    uint32_t sBo[8]; size_t gBo[8];
#pragma unroll
    for (int i = 0; i < 8; i++) {
        int u = i * 256 + tid, row = u >> 3, un = u & 7;
        sBo[i] = SWZ128((uint32_t)(row * 128 + un * 16));
        gBo[i] = (size_t)row * (KTOT * 2) + un * 16;
    }

    // ldmatrix lane geometry
    const int lr = lane & 15;             // A row-in-tile
    const int lc = lane >> 4;             // A k-unit select (0/1)
    const int lq = lane & 7;              // swizzle key
    const int brow_off = (lane & 7) + ((lane >> 4) << 3);  // B row-in-pair
    const int cub = (lane >> 3) & 1;      // B k-unit select

    float acc[4][8][4];
#pragma unroll
    for (int i = 0; i < 4; i++)
#pragma unroll
        for (int j = 0; j < 8; j++)
#pragma unroll
            for (int q = 0; q < 4; q++) acc[i][j][q] = 0.0f;

    // Prologue: fill stages 0,1
#pragma unroll
    for (int s = 0; s < NSTG - 1; s++) {
        uint32_t st = smem_base + s * STG;
#pragma unroll
        for (int i = 0; i < 4; i++) CP_ASYNC16(st + sAo[i], gA + gAo[i] + s * 128);
#pragma unroll
        for (int i = 0; i < 8; i++) CP_ASYNC16(st + A_ST + sBo[i], gB + gBo[i] + s * 128);
        CP_COMMIT();
    }

#pragma unroll 1
    for (int ck = 0; ck < NCH; ck++) {
        const int s = ck % NSTG;
        const uint32_t sa = smem_base + s * STG;
        const uint32_t sb = sa + A_ST;

        CP_WAIT1();
        __syncthreads();

#pragma unroll
        for (int kk = 0; kk < 4; kk++) {
            uint32_t a[4][4], b[4][4];
#pragma unroll
            for (int i = 0; i < 4; i++) {
                int row = wm * 64 + i * 16 + lr;
                ldsm_x4(a[i], sa + row * 128 + (((kk * 2 + lc) ^ lq) << 4));
            }
#pragma unroll
            for (int j = 0; j < 4; j++) {
                int row = wn * 64 + j * 16 + brow_off;
                ldsm_x4(b[j], sb + row * 128 + (((kk * 2 + cub) ^ lq) << 4));
            }
#pragma unroll
            for (int i = 0; i < 4; i++)
#pragma unroll
                for (int j = 0; j < 4; j++) {
                    mma_bf16(acc[i][2 * j],     a[i], b[j][0], b[j][1]);
                    mma_bf16(acc[i][2 * j + 1], a[i], b[j][2], b[j][3]);
                }
        }
        __syncthreads();

        const int nck = ck + NSTG - 1;
        if (nck < NCH) {
            const uint32_t st = smem_base + (nck % NSTG) * STG;
#pragma unroll
            for (int i = 0; i < 4; i++) CP_ASYNC16(st + sAo[i], gA + gAo[i] + (size_t)nck * 128);
#pragma unroll
            for (int i = 0; i < 8; i++) CP_ASYNC16(st + A_ST + sBo[i], gB + gBo[i] + (size_t)nck * 128);
            CP_COMMIT();
        }
    }

    // Epilogue
    const int do_sig = (n0 >= H_DIM);   // thirds are 1024-aligned, BN=256 divides
#pragma unroll
    for (int i = 0; i < 4; i++) {
        const int m = m0 + wm * 64 + i * 16 + (lane >> 2);
        float* r0 = g_u + (size_t)m * N_DIM;
        float* r1 = g_u + (size_t)(m + 8) * N_DIM;
#pragma unroll
        for (int t = 0; t < 8; t++) {
            const int n = n0 + wn * 64 + t * 8 + (lane & 3) * 2;
            const float b0 = __ldg(bias + n), b1 = __ldg(bias + n + 1);
            float v0 = acc[i][t][0] + b0, v1 = acc[i][t][1] + b1;
            float v2 = acc[i][t][2] + b0, v3 = acc[i][t][3] + b1;
            if (do_sig) {
                v0 = 1.0f / (1.0f + __expf(-v0));
                v1 = 1.0f / (1.0f + __expf(-v1));
                v2 = 1.0f / (1.0f + __expf(-v2));
                v3 = 1.0f / (1.0f + __expf(-v3));
            }
            *reinterpret_cast<float2*>(r0 + n) = make_float2(v0, v1);
            *reinterpret_cast<float2*>(r1 + n) = make_float2(v2, v3);
        }
    }
}

// ---------------------------------------------------------------------------
// Sequential SRU scan (one thread per (b,h) channel)
// ---------------------------------------------------------------------------
__global__ __launch_bounds__(64) void sru_scan_kernel(float* __restrict__ Hout) {
    const int idx = blockIdx.x * blockDim.x + threadIdx.x;
    const int b = idx >> 10;
    const int h = idx & (H_DIM - 1);

    const float* up = g_u + (size_t)b * T_DIM * N_DIM + h;
    float* op = Hout + (size_t)b * T_DIM * H_DIM + h;

    float c = 0.0f;
    for (int t = 0; t < T_DIM; t += 4) {
        float xt[4], ft[4], rt[4];
#pragma unroll
        for (int i = 0; i < 4; i++) {
            const float* p = up + (size_t)(t + i) * N_DIM;
            xt[i] = p[0];
            ft[i] = p[H_DIM];
            rt[i] = p[2 * H_DIM];
        }
#pragma unroll
        for (int i = 0; i < 4; i++) {
            const float g = (1.0f - ft[i]) * xt[i];
            c = fmaf(ft[i], c, g);
            const float hv = fmaf(rt[i], tanhf(c) - xt[i], xt[i]);
            op[(size_t)(t + i) * H_DIM] = hv;
        }
    }
}

// ---------------------------------------------------------------------------
extern "C" void kernel_launch(void* const* d_in, const int* in_sizes, int n_in,
                              void* d_out, int out_size) {
    const float* x = (const float*)d_in[0];
    const float* W = (const float*)d_in[1];
    const float* b = (const float*)d_in[2];
    float* out = (float*)d_out;

    cudaFuncSetAttribute(sru_gemm_mma_kernel,
                         cudaFuncAttributeMaxDynamicSharedMemorySize, GEMM_SMEM);

    convert_x_kernel<<<(M_DIM * K_DIM / 4) / 256, 256>>>(x);
    convert_w_kernel<<<dim3(N_DIM / 32, K_DIM / 32), dim3(32, 32)>>>(W);

    dim3 ggrid(N_DIM / BN, M_DIM / BM);   // (12, 256)
    sru_gemm_mma_kernel<<<ggrid, 256, GEMM_SMEM>>>(b);

    sru_scan_kernel<<<(B_DIM * H_DIM) / 64, 64>>>(out);
}

// round 4
// speedup vs baseline: 2.4810x; 1.1273x over previous
#include <cuda_runtime.h>
#include <cuda_bf16.h>
#include <math.h>
#include <stdint.h>

// Shapes (fixed by dataset)
#define M_DIM 32768
#define K_DIM 1024
#define N_DIM 3072
#define H_DIM 1024
#define T_DIM 2048
#define B_DIM 16

#define KTOT 3072            // virtual K' = 3 * 1024 (hi*hi + lo*hi + hi*lo)
#define BM 128
#define BN 256
#define BK 64                // bf16 elems per chunk = 128 bytes
#define NCH (KTOT / BK)      // 48
#define NSTG 4
#define A_ST (BM * 128)      // 16384 B per stage
#define B_ST (BN * 128)      // 32768 B per stage
#define STG (A_ST + B_ST)
#define GEMM_SMEM (NSTG * STG)   // 196608 B

// Scan chunking
#define TC 128
#define NCHK (T_DIM / TC)    // 16

// ---------------------------------------------------------------------------
// Static device scratch (cudaMalloc forbidden)
// ---------------------------------------------------------------------------
__device__ float g_u[(size_t)M_DIM * N_DIM];                         // 403 MB
__device__ __nv_bfloat16 g_a2[(size_t)M_DIM * 2 * K_DIM];            // 134 MB [m][hi|lo]
__device__ __nv_bfloat16 g_b2t[(size_t)N_DIM * 2 * K_DIM];           // 12.6 MB [n][hi|lo]
__device__ float g_F[NCHK * B_DIM * H_DIM];                          // 1 MB
__device__ float g_C[NCHK * B_DIM * H_DIM];                          // 1 MB
__device__ float g_cin[NCHK * B_DIM * H_DIM];                        // 1 MB

// ---------------------------------------------------------------------------
// PTX helpers (plain sm_103 features only: cp.async, ldmatrix, mma.sync)
// ---------------------------------------------------------------------------
__device__ __forceinline__ uint32_t smem_u32(const void* p) {
    uint32_t a;
    asm("{ .reg .u64 t; cvta.to.shared.u64 t, %1; cvt.u32.u64 %0, t; }" : "=r"(a) : "l"(p));
    return a;
}
#define CP_ASYNC16(s, g) asm volatile("cp.async.cg.shared.global [%0], [%1], 16;" :: "r"(s), "l"(g) : "memory")
#define CP_COMMIT() asm volatile("cp.async.commit_group;" ::: "memory")
#define CP_WAIT2()  asm volatile("cp.async.wait_group 2;" ::: "memory")

__device__ __forceinline__ void ldsm_x4(uint32_t* r, uint32_t addr) {
    asm volatile("ldmatrix.sync.aligned.m8n8.x4.shared.b16 {%0,%1,%2,%3}, [%4];"
                 : "=r"(r[0]), "=r"(r[1]), "=r"(r[2]), "=r"(r[3]) : "r"(addr));
}
__device__ __forceinline__ void mma_bf16(float* d, const uint32_t* a, uint32_t b0, uint32_t b1) {
    asm volatile("mma.sync.aligned.m16n8k16.row.col.f32.bf16.bf16.f32 "
                 "{%0,%1,%2,%3},{%4,%5,%6,%7},{%8,%9},{%0,%1,%2,%3};"
                 : "+f"(d[0]), "+f"(d[1]), "+f"(d[2]), "+f"(d[3])
                 : "r"(a[0]), "r"(a[1]), "r"(a[2]), "r"(a[3]), "r"(b0), "r"(b1));
}
#define SWZ128(off) ((off) ^ (((off) >> 3) & 0x70))

// chunk -> byte offset maps for the 3-product schedule
__device__ __forceinline__ int aoff_of(int ck) { return (ck < 32) ? ck : (ck - 32); }
__device__ __forceinline__ int boff_of(int ck) { return (ck < 16) ? ck : (ck - 16); }

// ---------------------------------------------------------------------------
// Conversions: hi/lo bf16 split, layout [hi(1024) | lo(1024)] per row
// ---------------------------------------------------------------------------
__global__ __launch_bounds__(256) void convert_x_kernel(const float* __restrict__ x) {
    size_t i = ((size_t)blockIdx.x * 256 + threadIdx.x) * 4;
    size_t m = i >> 10;
    int k = (int)(i & 1023);
    float4 v = *reinterpret_cast<const float4*>(x + i);
    const float* vp = &v.x;
    unsigned short hi[4], lo[4];
#pragma unroll
    for (int j = 0; j < 4; j++) {
        __nv_bfloat16 h = __float2bfloat16(vp[j]);
        __nv_bfloat16 l = __float2bfloat16(vp[j] - __bfloat162float(h));
        hi[j] = __bfloat16_as_ushort(h);
        lo[j] = __bfloat16_as_ushort(l);
    }
    uint2 hv = make_uint2((uint32_t)hi[0] | ((uint32_t)hi[1] << 16),
                          (uint32_t)hi[2] | ((uint32_t)hi[3] << 16));
    uint2 lv = make_uint2((uint32_t)lo[0] | ((uint32_t)lo[1] << 16),
                          (uint32_t)lo[2] | ((uint32_t)lo[3] << 16));
    __nv_bfloat16* base = g_a2 + m * 2048;
    *reinterpret_cast<uint2*>(base + k) = hv;              // hi
    *reinterpret_cast<uint2*>(base + 1024 + k) = lv;       // lo
}

__global__ __launch_bounds__(1024) void convert_w_kernel(const float* __restrict__ W) {
    __shared__ float s[32][33];
    int tx = threadIdx.x, ty = threadIdx.y;
    int n0 = blockIdx.x * 32, k0 = blockIdx.y * 32;
    s[ty][tx] = W[(size_t)(k0 + ty) * N_DIM + n0 + tx];
    __syncthreads();
    float v = s[tx][ty];                 // W[k0+tx][n0+ty]
    __nv_bfloat16 h = __float2bfloat16(v);
    __nv_bfloat16 l = __float2bfloat16(v - __bfloat162float(h));
    __nv_bfloat16* base = g_b2t + (size_t)(n0 + ty) * 2048;
    base[k0 + tx] = h;                   // hi
    base[1024 + k0 + tx] = l;            // lo
}

// ---------------------------------------------------------------------------
// mma.sync bf16 GEMM: CTA 128x256, warp 64x64, BK=64, 4-stage cp.async,
// one barrier per chunk, prefetch issued 3 chunks ahead before compute.
// ---------------------------------------------------------------------------
__global__ __launch_bounds__(256, 1) void sru_gemm_mma_kernel(const float* __restrict__ bias) {
    extern __shared__ __align__(1024) char dsmem[];
    const uint32_t smem_base = smem_u32(dsmem);

    const int tid = threadIdx.x;
    const int lane = tid & 31;
    const int wid = tid >> 5;
    const int wm = wid & 1;          // 2 warps along M
    const int wn = wid >> 1;         // 4 warps along N
    const int m0 = blockIdx.y * BM;
    const int n0 = blockIdx.x * BN;

    const char* gA = reinterpret_cast<const char*>(g_a2) + (size_t)m0 * 4096;
    const char* gB = reinterpret_cast<const char*>(g_b2t) + (size_t)n0 * 4096;

    // Per-thread cp.async offsets (row pitch 128 B in smem, 4096 B in gmem)
    uint32_t sAo[4]; size_t gAo[4];
#pragma unroll
    for (int i = 0; i < 4; i++) {
        int u = i * 256 + tid, row = u >> 3, un = u & 7;
        sAo[i] = SWZ128((uint32_t)(row * 128 + un * 16));
        gAo[i] = (size_t)row * 4096 + un * 16;
    }
    uint32_t sBo[8]; size_t gBo[8];
#pragma unroll
    for (int i = 0; i < 8; i++) {
        int u = i * 256 + tid, row = u >> 3, un = u & 7;
        sBo[i] = SWZ128((uint32_t)(row * 128 + un * 16));
        gBo[i] = (size_t)row * 4096 + un * 16;
    }

    // ldmatrix lane geometry
    const int lr = lane & 15;
    const int lc = lane >> 4;
    const int lq = lane & 7;
    const int brow_off = (lane & 7) + ((lane >> 4) << 3);
    const int cub = (lane >> 3) & 1;

    float acc[4][8][4];
#pragma unroll
    for (int i = 0; i < 4; i++)
#pragma unroll
        for (int j = 0; j < 8; j++)
#pragma unroll
            for (int q = 0; q < 4; q++) acc[i][j][q] = 0.0f;

    // Prologue: fill stages 0,1,2
#pragma unroll
    for (int s = 0; s < NSTG - 1; s++) {
        uint32_t st = smem_base + s * STG;
        size_t ao = (size_t)aoff_of(s) * 128, bo = (size_t)boff_of(s) * 128;
#pragma unroll
        for (int i = 0; i < 4; i++) CP_ASYNC16(st + sAo[i], gA + gAo[i] + ao);
#pragma unroll
        for (int i = 0; i < 8; i++) CP_ASYNC16(st + A_ST + sBo[i], gB + gBo[i] + bo);
        CP_COMMIT();
    }

#pragma unroll 1
    for (int ck = 0; ck < NCH; ck++) {
        const uint32_t sa = smem_base + (ck % NSTG) * STG;
        const uint32_t sb = sa + A_ST;

        CP_WAIT2();            // chunk ck arrived (<=2 groups pending)
        __syncthreads();       // all warps done with stage (ck-1)%NSTG == (ck+3)%NSTG

        // Prefetch chunk ck+3 (overlaps with compute of ck)
        const int nck = ck + NSTG - 1;
        if (nck < NCH) {
            const uint32_t st = smem_base + (nck % NSTG) * STG;
            size_t ao = (size_t)aoff_of(nck) * 128, bo = (size_t)boff_of(nck) * 128;
#pragma unroll
            for (int i = 0; i < 4; i++) CP_ASYNC16(st + sAo[i], gA + gAo[i] + ao);
#pragma unroll
            for (int i = 0; i < 8; i++) CP_ASYNC16(st + A_ST + sBo[i], gB + gBo[i] + bo);
        }
        CP_COMMIT();           // unconditional: keeps group accounting aligned

#pragma unroll
        for (int kk = 0; kk < 4; kk++) {
            uint32_t a[4][4], b[4][4];
#pragma unroll
            for (int i = 0; i < 4; i++) {
                int row = wm * 64 + i * 16 + lr;
                ldsm_x4(a[i], sa + row * 128 + (((kk * 2 + lc) ^ lq) << 4));
            }
#pragma unroll
            for (int j = 0; j < 4; j++) {
                int row = wn * 64 + j * 16 + brow_off;
                ldsm_x4(b[j], sb + row * 128 + (((kk * 2 + cub) ^ lq) << 4));
            }
#pragma unroll
            for (int i = 0; i < 4; i++)
#pragma unroll
                for (int j = 0; j < 4; j++) {
                    mma_bf16(acc[i][2 * j],     a[i], b[j][0], b[j][1]);
                    mma_bf16(acc[i][2 * j + 1], a[i], b[j][2], b[j][3]);
                }
        }
    }

    // Epilogue: +bias, sigmoid on n >= 1024
    const int do_sig = (n0 >= H_DIM);
#pragma unroll
    for (int i = 0; i < 4; i++) {
        const int m = m0 + wm * 64 + i * 16 + (lane >> 2);
        float* r0 = g_u + (size_t)m * N_DIM;
        float* r1 = g_u + (size_t)(m + 8) * N_DIM;
#pragma unroll
        for (int t = 0; t < 8; t++) {
            const int n = n0 + wn * 64 + t * 8 + (lane & 3) * 2;
            const float b0 = __ldg(bias + n), b1 = __ldg(bias + n + 1);
            float v0 = acc[i][t][0] + b0, v1 = acc[i][t][1] + b1;
            float v2 = acc[i][t][2] + b0, v3 = acc[i][t][3] + b1;
            if (do_sig) {
                v0 = 1.0f / (1.0f + __expf(-v0));
                v1 = 1.0f / (1.0f + __expf(-v1));
                v2 = 1.0f / (1.0f + __expf(-v2));
                v3 = 1.0f / (1.0f + __expf(-v3));
            }
            *reinterpret_cast<float2*>(r0 + n) = make_float2(v0, v1);
            *reinterpret_cast<float2*>(r1 + n) = make_float2(v2, v3);
        }
    }
}

// ---------------------------------------------------------------------------
// Chunked scan. Recurrence is affine in c: c_end = (prod f) * c_in + c_local.
// Pass 1: per (chunk,b,h) compute F = prod f and c_local (c_in = 0).
// Combine: per (b,h) serial over 16 chunks -> entry state per chunk.
// Pass 2: replay each chunk from its entry state, write h.
// ---------------------------------------------------------------------------
__global__ __launch_bounds__(128) void scan_pass1_kernel() {
    const int h = blockIdx.x * 128 + threadIdx.x;
    const int b = blockIdx.y;
    const int j = blockIdx.z;

    const float* up = g_u + ((size_t)b * T_DIM + (size_t)j * TC) * N_DIM + h;
    float c = 0.0f, F = 1.0f;
#pragma unroll 1
    for (int t = 0; t < TC; t += 4) {
        float xt[4], ft[4];
#pragma unroll
        for (int i = 0; i < 4; i++) {
            const float* p = up + (size_t)(t + i) * N_DIM;
            xt[i] = p[0];
            ft[i] = p[H_DIM];
        }
#pragma unroll
        for (int i = 0; i < 4; i++) {
            c = fmaf(ft[i], c, (1.0f - ft[i]) * xt[i]);
            F *= ft[i];
        }
    }
    const size_t o = ((size_t)j * B_DIM + b) * H_DIM + h;
    g_F[o] = F;
    g_C[o] = c;
}

__global__ __launch_bounds__(256) void scan_combine_kernel() {
    const int idx = blockIdx.x * 256 + threadIdx.x;   // 0..16383 = b*1024+h
    float c = 0.0f;
#pragma unroll
    for (int j = 0; j < NCHK; j++) {
        const size_t o = (size_t)j * (B_DIM * H_DIM) + idx;
        g_cin[o] = c;
        c = fmaf(g_F[o], c, g_C[o]);
    }
}

__global__ __launch_bounds__(128) void scan_pass2_kernel(float* __restrict__ Hout) {
    const int h = blockIdx.x * 128 + threadIdx.x;
    const int b = blockIdx.y;
    const int j = blockIdx.z;

    const float* up = g_u + ((size_t)b * T_DIM + (size_t)j * TC) * N_DIM + h;
    float* op = Hout + ((size_t)b * T_DIM + (size_t)j * TC) * H_DIM + h;

    float c = g_cin[((size_t)j * B_DIM + b) * H_DIM + h];
#pragma unroll 1
    for (int t = 0; t < TC; t += 4) {
        float xt[4], ft[4], rt[4];
#pragma unroll
        for (int i = 0; i < 4; i++) {
            const float* p = up + (size_t)(t + i) * N_DIM;
            xt[i] = p[0];
            ft[i] = p[H_DIM];
            rt[i] = p[2 * H_DIM];
        }
#pragma unroll
        for (int i = 0; i < 4; i++) {
            c = fmaf(ft[i], c, (1.0f - ft[i]) * xt[i]);
            op[(size_t)(t + i) * H_DIM] = fmaf(rt[i], tanhf(c) - xt[i], xt[i]);
        }
    }
}

// ---------------------------------------------------------------------------
extern "C" void kernel_launch(void* const* d_in, const int* in_sizes, int n_in,
                              void* d_out, int out_size) {
    const float* x = (const float*)d_in[0];
    const float* W = (const float*)d_in[1];
    const float* b = (const float*)d_in[2];
    float* out = (float*)d_out;

    cudaFuncSetAttribute(sru_gemm_mma_kernel,
                         cudaFuncAttributeMaxDynamicSharedMemorySize, GEMM_SMEM);

    convert_x_kernel<<<(M_DIM * K_DIM / 4) / 256, 256>>>(x);
    convert_w_kernel<<<dim3(N_DIM / 32, K_DIM / 32), dim3(32, 32)>>>(W);

    dim3 ggrid(N_DIM / BN, M_DIM / BM);   // (12, 256)
    sru_gemm_mma_kernel<<<ggrid, 256, GEMM_SMEM>>>(b);

    dim3 sgrid(H_DIM / 128, B_DIM, NCHK); // (8, 16, 16)
    scan_pass1_kernel<<<sgrid, 128>>>();
    scan_combine_kernel<<<(B_DIM * H_DIM) / 256, 256>>>();
    scan_pass2_kernel<<<sgrid, 128>>>(out);
}